// round 11
// baseline (speedup 1.0000x reference)
#include <cuda_runtime.h>
#include <math.h>
#include <stdint.h>

#define B_   4
#define L_   1024
#define DM   256
#define DI   512
#define NS   16
#define DTR  16
#define KC   4
#define NL   8
#define ROWS (B_*L_)

// ---------------- static scratch (no allocs allowed) ----------------
__device__ float g_h[ROWS*DM];        // residual stream
__device__ float g_xn[ROWS*DM];       // rmsnorm output
__device__ float g_hidgate[ROWS*2*DI];// in-proj output: [hid | gate]
__device__ float g_hid[ROWS*DI];      // post conv+silu
__device__ float g_sp[ROWS*48];       // [dt(16) | B(16) | C(16)]
__device__ float g_y[ROWS*DI];        // scan output (gated)

// ---------------- tf32 helpers (identical to R4) ----------------
__device__ __forceinline__ uint32_t f2tf32(float x) {
    uint32_t r;
    asm("cvt.rna.tf32.f32 %0, %1;" : "=r"(r) : "f"(x));
    return r;
}
__device__ __forceinline__ void split_tf32(float x, uint32_t& hi, uint32_t& lo) {
    hi = f2tf32(x);
    float hif = __uint_as_float(hi);
    lo = f2tf32(x - hif);
}
__device__ __forceinline__ void mma_tf32(float& c0, float& c1, float& c2, float& c3,
                                         uint32_t a0, uint32_t a1, uint32_t a2, uint32_t a3,
                                         uint32_t b0, uint32_t b1) {
    asm volatile(
        "mma.sync.aligned.m16n8k8.row.col.f32.tf32.tf32.f32 "
        "{%0,%1,%2,%3}, {%4,%5,%6,%7}, {%8,%9}, {%0,%1,%2,%3};"
        : "+f"(c0), "+f"(c1), "+f"(c2), "+f"(c3)
        : "r"(a0), "r"(a1), "r"(a2), "r"(a3), "r"(b0), "r"(b1));
}

// ================= tf32-split GEMM — R4 skeleton, splits at STAGING =================
// C[M,N] = A[M,K] @ W[K,N] (+Res if RES). 256 threads, 64x64 tile.
// Reads the SAME f32 globals as R4; splits computed in-kernel at staging time.
// smem layouts are R4's proven-conflict-free shapes, duplicated for hi/lo.
template<int N_, int K_, bool RES>
__device__ __forceinline__ void mma_gemm_body(const float* __restrict__ A,
                                              const float* __restrict__ Bw,
                                              float* C, const float* Res) {
    __shared__ uint32_t Ash[64][36], Asl[64][36];
    __shared__ uint32_t Bsh[32][72], Bsl[32][72];
    const int tid  = threadIdx.x;
    const int lane = tid & 31;
    const int warp = tid >> 5;
    const int wr   = warp & 3;     // warp row: 16 rows each
    const int wc   = warp >> 2;    // warp col: 32 cols each
    const int g    = lane >> 2;
    const int t    = lane & 3;
    const int row0 = blockIdx.y * 64;
    const int col0 = blockIdx.x * 64;

    float acc[4][4];
    #pragma unroll
    for (int nt = 0; nt < 4; nt++)
        #pragma unroll
        for (int q = 0; q < 4; q++) acc[nt][q] = 0.f;

    for (int k0 = 0; k0 < K_; k0 += 32) {
        // stage A: 64x32 f32 as float4 (512 float4, 2/thread), split to hi/lo
        #pragma unroll
        for (int it = 0; it < 2; it++) {
            int idx = tid + it*256;
            int r = idx >> 3, k4 = idx & 7;
            float4 v = *reinterpret_cast<const float4*>(
                A + (size_t)(row0 + r)*K_ + k0 + k4*4);
            uint32_t h0,l0,h1,l1,h2,l2,h3,l3;
            split_tf32(v.x, h0, l0);
            split_tf32(v.y, h1, l1);
            split_tf32(v.z, h2, l2);
            split_tf32(v.w, h3, l3);
            Ash[r][k4*4+0] = h0; Asl[r][k4*4+0] = l0;
            Ash[r][k4*4+1] = h1; Asl[r][k4*4+1] = l1;
            Ash[r][k4*4+2] = h2; Asl[r][k4*4+2] = l2;
            Ash[r][k4*4+3] = h3; Asl[r][k4*4+3] = l3;
        }
        // stage B: 32x64 f32 as float4 (512 float4, 2/thread), guard N, split
        #pragma unroll
        for (int it = 0; it < 2; it++) {
            int idx = tid + it*256;
            int k = idx >> 4, n4 = idx & 15;
            int gn = col0 + n4*4;
            float4 v;
            if ((N_ & 63) == 0 || gn + 3 < N_)
                v = *reinterpret_cast<const float4*>(Bw + (size_t)(k0 + k)*N_ + gn);
            else
                v = make_float4(0.f, 0.f, 0.f, 0.f);
            uint32_t h0,l0,h1,l1,h2,l2,h3,l3;
            split_tf32(v.x, h0, l0);
            split_tf32(v.y, h1, l1);
            split_tf32(v.z, h2, l2);
            split_tf32(v.w, h3, l3);
            Bsh[k][n4*4+0] = h0; Bsl[k][n4*4+0] = l0;
            Bsh[k][n4*4+1] = h1; Bsl[k][n4*4+1] = l1;
            Bsh[k][n4*4+2] = h2; Bsl[k][n4*4+2] = l2;
            Bsh[k][n4*4+3] = h3; Bsl[k][n4*4+3] = l3;
        }
        __syncthreads();

        #pragma unroll
        for (int ks = 0; ks < 4; ks++) {
            const int rb = wr*16 + g;
            const int kk = ks*8 + t;
            uint32_t ah[4], al[4];
            ah[0] = Ash[rb    ][kk    ];  al[0] = Asl[rb    ][kk    ];
            ah[1] = Ash[rb + 8][kk    ];  al[1] = Asl[rb + 8][kk    ];
            ah[2] = Ash[rb    ][kk + 4];  al[2] = Asl[rb    ][kk + 4];
            ah[3] = Ash[rb + 8][kk + 4];  al[3] = Asl[rb + 8][kk + 4];
            #pragma unroll
            for (int nt = 0; nt < 4; nt++) {
                const int cb = wc*32 + nt*8 + g;
                uint32_t bh0 = Bsh[ks*8 + t    ][cb];
                uint32_t bh1 = Bsh[ks*8 + t + 4][cb];
                uint32_t bl0 = Bsl[ks*8 + t    ][cb];
                uint32_t bl1 = Bsl[ks*8 + t + 4][cb];
                mma_tf32(acc[nt][0], acc[nt][1], acc[nt][2], acc[nt][3],
                         ah[0], ah[1], ah[2], ah[3], bh0, bh1);
                mma_tf32(acc[nt][0], acc[nt][1], acc[nt][2], acc[nt][3],
                         ah[0], ah[1], ah[2], ah[3], bl0, bl1);
                mma_tf32(acc[nt][0], acc[nt][1], acc[nt][2], acc[nt][3],
                         al[0], al[1], al[2], al[3], bh0, bh1);
            }
        }
        __syncthreads();
    }

    // epilogue (R4): c0:(r,2q) c1:(r,2q+1) c2/c3:(+8 rows)
    const int r0 = row0 + wr*16 + g;
    #pragma unroll
    for (int nt = 0; nt < 4; nt++) {
        const int cbase = col0 + wc*32 + nt*8 + 2*t;
        #pragma unroll
        for (int h = 0; h < 2; h++) {
            int gm = r0 + h*8;
            #pragma unroll
            for (int q = 0; q < 2; q++) {
                int gn = cbase + q;
                if ((N_ & 63) == 0 || gn < N_) {
                    float v = acc[nt][h*2 + q];
                    if (RES) v += Res[(size_t)gm*N_ + gn];
                    C[(size_t)gm*N_ + gn] = v;
                }
            }
        }
    }
}

__global__ void __launch_bounds__(256) gemm_in_k(const float* __restrict__ W) {
    mma_gemm_body<2*DI, DM, false>(g_xn, W, g_hidgate, nullptr);
}
__global__ void __launch_bounds__(256) gemm_x_k(const float* __restrict__ W) {
    mma_gemm_body<48, DI, false>(g_hid, W, g_sp, nullptr);
}
__global__ void __launch_bounds__(256) gemm_out_k(const float* __restrict__ W) {
    mma_gemm_body<DM, DI, true>(g_y, W, g_h, g_h);
}

// ---------------- embed ----------------
__global__ void embed_kernel(const float* __restrict__ x,
                             const float* __restrict__ pos,
                             const float* __restrict__ We,
                             const float* __restrict__ be) {
    int row = blockIdx.x;          // 0..4095
    int j   = threadIdx.x;         // 0..127
    int l   = row & (L_-1);
    float x0 = x[row*2+0], x1 = x[row*2+1];
    g_h[(size_t)row*DM + j]       = x0*We[j] + x1*We[128+j] + be[j];
    g_h[(size_t)row*DM + 128 + j] = pos[l*128 + j];
}

// ---------------- rmsnorm ----------------
__global__ void __launch_bounds__(256) rmsnorm_kernel(const float* __restrict__ w) {
    int row = blockIdx.x, tid = threadIdx.x;
    float v = g_h[(size_t)row*DM + tid];
    float ss = v*v;
    #pragma unroll
    for (int o = 16; o > 0; o >>= 1) ss += __shfl_xor_sync(0xffffffffu, ss, o);
    __shared__ float red[8];
    if ((tid & 31) == 0) red[tid >> 5] = ss;
    __syncthreads();
    float tot = 0.f;
    #pragma unroll
    for (int i = 0; i < 8; i++) tot += red[i];
    float scale = rsqrtf(tot * (1.f/DM) + 1e-5f);
    g_xn[(size_t)row*DM + tid] = v * scale * w[tid];
}

// ---------------- causal depthwise conv (K=4) + silu ----------------
__global__ void __launch_bounds__(256) conv_silu_kernel(const float* __restrict__ cw,
                                                        const float* __restrict__ cb) {
    int idx = blockIdx.x*256 + threadIdx.x;      // over ROWS*DI
    int d   = idx & (DI-1);
    int row = idx >> 9;
    int l   = row & (L_-1);
    float c0 = cw[d*KC+0], c1 = cw[d*KC+1], c2 = cw[d*KC+2], c3 = cw[d*KC+3];
    const float* base = g_hidgate + (size_t)row*(2*DI) + d;
    float acc = cb[d];
    if (l >= 3) acc = fmaf(base[-3*2*DI], c0, acc);
    if (l >= 2) acc = fmaf(base[-2*2*DI], c1, acc);
    if (l >= 1) acc = fmaf(base[-1*2*DI], c2, acc);
    acc = fmaf(base[0], c3, acc);
    g_hid[idx] = acc / (1.f + __expf(-acc));     // silu
}

// ---------------- selective scan (delta fused) + skip + gate ----------------
// block = (b, 16-channel d-tile); threads: n = tid&15, dl = tid>>4
#define CH 16
__global__ void __launch_bounds__(256) scan_kernel(const float* __restrict__ Alog,
                                                   const float* __restrict__ Dsk,
                                                   const float* __restrict__ Wdt,
                                                   const float* __restrict__ bdt) {
    const int b    = blockIdx.x >> 5;     // DI/16 = 32 tiles
    const int dblk = blockIdx.x & 31;
    const int tid  = threadIdx.x;
    const int n    = tid & 15;
    const int dl   = tid >> 4;
    const int d    = dblk*16 + dl;
    const float A  = -__expf(Alog[d*NS + n]);
    const float Dskip = Dsk[d];
    float h = 0.f;
    __shared__ float s_Wdt[DTR][17], s_bdt[16];
    __shared__ float s_dt[CH][16], s_delta[CH][16], s_hid[CH][16], s_B[CH][16],
                     s_C[CH][16], s_gate[CH][16], s_y[CH][16];
    {   // preload delta weights for this 16-channel tile
        int r = tid >> 4, c = tid & 15;
        s_Wdt[r][c] = Wdt[r*DI + dblk*16 + c];
        if (tid < 16) s_bdt[tid] = bdt[dblk*16 + tid];
    }
    __syncthreads();

    for (int t0 = 0; t0 < L_; t0 += CH) {
        __syncthreads();
        {   // stage CH timesteps; 256 threads, one element each per array
            int tt = tid >> 4, c = tid & 15;
            int row = b*L_ + t0 + tt;
            s_dt[tt][c]   = g_sp[row*48 + c];
            s_hid[tt][c]  = g_hid[(size_t)row*DI + dblk*16 + c];
            s_B[tt][c]    = g_sp[row*48 + DTR + c];
            s_C[tt][c]    = g_sp[row*48 + DTR + NS + c];
            s_gate[tt][c] = g_hidgate[(size_t)row*(2*DI) + DI + dblk*16 + c];
        }
        __syncthreads();
        {   // fused delta = softplus(dt @ Wdt + b_dt), same fmaf order as R4
            int tt = tid >> 4, c = tid & 15;
            float acc = s_bdt[c];
            #pragma unroll
            for (int r = 0; r < DTR; r++) acc = fmaf(s_dt[tt][r], s_Wdt[r][c], acc);
            s_delta[tt][c] = (acc > 20.f) ? acc : log1pf(__expf(acc));
        }
        __syncthreads();
        #pragma unroll
        for (int tt = 0; tt < CH; tt++) {
            float de  = s_delta[tt][dl];
            float dA  = __expf(de * A);
            float dBu = de * s_B[tt][n] * s_hid[tt][dl];
            h = fmaf(dA, h, dBu);
            float contrib = h * s_C[tt][n];
            contrib += __shfl_xor_sync(0xffffffffu, contrib, 1);
            contrib += __shfl_xor_sync(0xffffffffu, contrib, 2);
            contrib += __shfl_xor_sync(0xffffffffu, contrib, 4);
            contrib += __shfl_xor_sync(0xffffffffu, contrib, 8);
            if (n == 0) {
                float yv = contrib + s_hid[tt][dl]*Dskip;
                float g  = s_gate[tt][dl];
                s_y[tt][dl] = yv * g / (1.f + __expf(-g));
            }
        }
        __syncthreads();
        {   // coalesced write of gated scan output
            int tt = tid >> 4, c = tid & 15;
            int row = b*L_ + t0 + tt;
            g_y[(size_t)row*DI + dblk*16 + c] = s_y[tt][c];
        }
    }
}

// ---------------- output head ----------------
__global__ void __launch_bounds__(256) head_kernel(const float* __restrict__ Wa,
                                                   const float* __restrict__ ba,
                                                   const float* __restrict__ Wp,
                                                   const float* __restrict__ bp,
                                                   float* __restrict__ out) {
    int row = blockIdx.x, tid = threadIdx.x;
    float v  = g_h[(size_t)row*DM + tid];
    float pa = v * Wa[tid];
    float pp = v * Wp[tid];
    #pragma unroll
    for (int o = 16; o > 0; o >>= 1) {
        pa += __shfl_xor_sync(0xffffffffu, pa, o);
        pp += __shfl_xor_sync(0xffffffffu, pp, o);
    }
    __shared__ float ra[8], rp[8];
    if ((tid & 31) == 0) { ra[tid>>5] = pa; rp[tid>>5] = pp; }
    __syncthreads();
    if (tid == 0) {
        float sa = 0.f, sp2 = 0.f;
        #pragma unroll
        for (int i = 0; i < 8; i++) { sa += ra[i]; sp2 += rp[i]; }
        out[row*2+0] = sa + ba[0];
        out[row*2+1] = tanhf(sp2 + bp[0]);
    }
}

// ---------------- launch ----------------
extern "C" void kernel_launch(void* const* d_in, const int* in_sizes, int n_in,
                              void* d_out, int out_size) {
    const float* x       = (const float*)d_in[0];
    const float* pos     = (const float*)d_in[1];
    const float* W_embed = (const float*)d_in[2];
    const float* b_embed = (const float*)d_in[3];
    const float* ln_w    = (const float*)d_in[4];
    const float* W_in    = (const float*)d_in[5];
    const float* conv_w  = (const float*)d_in[6];
    const float* conv_b  = (const float*)d_in[7];
    const float* W_x     = (const float*)d_in[8];
    const float* W_dt    = (const float*)d_in[9];
    const float* b_dt    = (const float*)d_in[10];
    const float* A_log   = (const float*)d_in[11];
    const float* D_skip  = (const float*)d_in[12];
    const float* W_out   = (const float*)d_in[13];
    const float* W_amp   = (const float*)d_in[14];
    const float* b_amp   = (const float*)d_in[15];
    const float* W_phase = (const float*)d_in[16];
    const float* b_phase = (const float*)d_in[17];

    embed_kernel<<<ROWS, 128>>>(x, pos, W_embed, b_embed);

    for (int i = 0; i < NL; i++) {
        rmsnorm_kernel<<<ROWS, 256>>>(ln_w + (size_t)i*DM);
        gemm_in_k<<<dim3((2*DI)/64, ROWS/64), 256>>>(W_in + (size_t)i*DM*2*DI);
        conv_silu_kernel<<<(ROWS*DI)/256, 256>>>(conv_w + (size_t)i*DI*KC,
                                                 conv_b + (size_t)i*DI);
        gemm_x_k<<<dim3(1, ROWS/64), 256>>>(W_x + (size_t)i*DI*48);
        scan_kernel<<<B_*(DI/16), 256>>>(A_log + (size_t)i*DI*NS,
                                         D_skip + (size_t)i*DI,
                                         W_dt + (size_t)i*DTR*DI,
                                         b_dt + (size_t)i*DI);
        gemm_out_k<<<dim3(DM/64, ROWS/64), 256>>>(W_out + (size_t)i*DI*DM);
    }

    head_kernel<<<ROWS, 256>>>(W_amp, b_amp, W_phase, b_phase, (float*)d_out);
}

// round 12
// speedup vs baseline: 1.5431x; 1.5431x over previous
#include <cuda_runtime.h>
#include <math.h>
#include <stdint.h>

#define B_   4
#define L_   1024
#define DM   256
#define DI   512
#define NS   16
#define DTR  16
#define KC   4
#define NL   8
#define ROWS (B_*L_)
#define SEG  8
#define SEGLEN (L_/SEG)   // 128

// ---------------- static scratch (no allocs allowed) ----------------
__device__ float g_h[ROWS*DM];        // residual stream
__device__ float g_xn[ROWS*DM];       // rmsnorm output
__device__ float g_hidgate[ROWS*2*DI];// in-proj output: [hid | gate]
__device__ float g_hid[ROWS*DI];      // post conv+silu
__device__ float g_sp[ROWS*48];       // [dt(16) | B(16) | C(16)]
__device__ float g_delta[ROWS*DI];    // softplus(dt@Wdt + b)
__device__ float g_y[ROWS*DI];        // scan output (gated)
__device__ float g_segP[B_*32*SEG*256];  // per-segment prod(dA) per (d,n)
__device__ float g_segH[B_*32*SEG*256];  // per-segment local final h per (d,n)

// ---------------- tf32 helpers (identical to R4/R11) ----------------
__device__ __forceinline__ uint32_t f2tf32(float x) {
    uint32_t r;
    asm("cvt.rna.tf32.f32 %0, %1;" : "=r"(r) : "f"(x));
    return r;
}
__device__ __forceinline__ void split_tf32(float x, uint32_t& hi, uint32_t& lo) {
    hi = f2tf32(x);
    float hif = __uint_as_float(hi);
    lo = f2tf32(x - hif);
}
__device__ __forceinline__ void mma_tf32(float& c0, float& c1, float& c2, float& c3,
                                         uint32_t a0, uint32_t a1, uint32_t a2, uint32_t a3,
                                         uint32_t b0, uint32_t b1) {
    asm volatile(
        "mma.sync.aligned.m16n8k8.row.col.f32.tf32.tf32.f32 "
        "{%0,%1,%2,%3}, {%4,%5,%6,%7}, {%8,%9}, {%0,%1,%2,%3};"
        : "+f"(c0), "+f"(c1), "+f"(c2), "+f"(c3)
        : "r"(a0), "r"(a1), "r"(a2), "r"(a3), "r"(b0), "r"(b1));
}

// ================= tf32-split GEMM — identical to R11 (passed) =================
template<int N_, int K_, bool RES>
__device__ __forceinline__ void mma_gemm_body(const float* __restrict__ A,
                                              const float* __restrict__ Bw,
                                              float* C, const float* Res) {
    __shared__ uint32_t Ash[64][36], Asl[64][36];
    __shared__ uint32_t Bsh[32][72], Bsl[32][72];
    const int tid  = threadIdx.x;
    const int lane = tid & 31;
    const int warp = tid >> 5;
    const int wr   = warp & 3;
    const int wc   = warp >> 2;
    const int g    = lane >> 2;
    const int t    = lane & 3;
    const int row0 = blockIdx.y * 64;
    const int col0 = blockIdx.x * 64;

    float acc[4][4];
    #pragma unroll
    for (int nt = 0; nt < 4; nt++)
        #pragma unroll
        for (int q = 0; q < 4; q++) acc[nt][q] = 0.f;

    for (int k0 = 0; k0 < K_; k0 += 32) {
        #pragma unroll
        for (int it = 0; it < 2; it++) {
            int idx = tid + it*256;
            int r = idx >> 3, k4 = idx & 7;
            float4 v = *reinterpret_cast<const float4*>(
                A + (size_t)(row0 + r)*K_ + k0 + k4*4);
            uint32_t h0,l0,h1,l1,h2,l2,h3,l3;
            split_tf32(v.x, h0, l0);
            split_tf32(v.y, h1, l1);
            split_tf32(v.z, h2, l2);
            split_tf32(v.w, h3, l3);
            Ash[r][k4*4+0] = h0; Asl[r][k4*4+0] = l0;
            Ash[r][k4*4+1] = h1; Asl[r][k4*4+1] = l1;
            Ash[r][k4*4+2] = h2; Asl[r][k4*4+2] = l2;
            Ash[r][k4*4+3] = h3; Asl[r][k4*4+3] = l3;
        }
        #pragma unroll
        for (int it = 0; it < 2; it++) {
            int idx = tid + it*256;
            int k = idx >> 4, n4 = idx & 15;
            int gn = col0 + n4*4;
            float4 v;
            if ((N_ & 63) == 0 || gn + 3 < N_)
                v = *reinterpret_cast<const float4*>(Bw + (size_t)(k0 + k)*N_ + gn);
            else
                v = make_float4(0.f, 0.f, 0.f, 0.f);
            uint32_t h0,l0,h1,l1,h2,l2,h3,l3;
            split_tf32(v.x, h0, l0);
            split_tf32(v.y, h1, l1);
            split_tf32(v.z, h2, l2);
            split_tf32(v.w, h3, l3);
            Bsh[k][n4*4+0] = h0; Bsl[k][n4*4+0] = l0;
            Bsh[k][n4*4+1] = h1; Bsl[k][n4*4+1] = l1;
            Bsh[k][n4*4+2] = h2; Bsl[k][n4*4+2] = l2;
            Bsh[k][n4*4+3] = h3; Bsl[k][n4*4+3] = l3;
        }
        __syncthreads();

        #pragma unroll
        for (int ks = 0; ks < 4; ks++) {
            const int rb = wr*16 + g;
            const int kk = ks*8 + t;
            uint32_t ah[4], al[4];
            ah[0] = Ash[rb    ][kk    ];  al[0] = Asl[rb    ][kk    ];
            ah[1] = Ash[rb + 8][kk    ];  al[1] = Asl[rb + 8][kk    ];
            ah[2] = Ash[rb    ][kk + 4];  al[2] = Asl[rb    ][kk + 4];
            ah[3] = Ash[rb + 8][kk + 4];  al[3] = Asl[rb + 8][kk + 4];
            #pragma unroll
            for (int nt = 0; nt < 4; nt++) {
                const int cb = wc*32 + nt*8 + g;
                uint32_t bh0 = Bsh[ks*8 + t    ][cb];
                uint32_t bh1 = Bsh[ks*8 + t + 4][cb];
                uint32_t bl0 = Bsl[ks*8 + t    ][cb];
                uint32_t bl1 = Bsl[ks*8 + t + 4][cb];
                mma_tf32(acc[nt][0], acc[nt][1], acc[nt][2], acc[nt][3],
                         ah[0], ah[1], ah[2], ah[3], bh0, bh1);
                mma_tf32(acc[nt][0], acc[nt][1], acc[nt][2], acc[nt][3],
                         ah[0], ah[1], ah[2], ah[3], bl0, bl1);
                mma_tf32(acc[nt][0], acc[nt][1], acc[nt][2], acc[nt][3],
                         al[0], al[1], al[2], al[3], bh0, bh1);
            }
        }
        __syncthreads();
    }

    const int r0 = row0 + wr*16 + g;
    #pragma unroll
    for (int nt = 0; nt < 4; nt++) {
        const int cbase = col0 + wc*32 + nt*8 + 2*t;
        #pragma unroll
        for (int h = 0; h < 2; h++) {
            int gm = r0 + h*8;
            #pragma unroll
            for (int q = 0; q < 2; q++) {
                int gn = cbase + q;
                if ((N_ & 63) == 0 || gn < N_) {
                    float v = acc[nt][h*2 + q];
                    if (RES) v += Res[(size_t)gm*N_ + gn];
                    C[(size_t)gm*N_ + gn] = v;
                }
            }
        }
    }
}

__global__ void __launch_bounds__(256) gemm_in_k(const float* __restrict__ W) {
    mma_gemm_body<2*DI, DM, false>(g_xn, W, g_hidgate, nullptr);
}
__global__ void __launch_bounds__(256) gemm_x_k(const float* __restrict__ W) {
    mma_gemm_body<48, DI, false>(g_hid, W, g_sp, nullptr);
}
__global__ void __launch_bounds__(256) gemm_out_k(const float* __restrict__ W) {
    mma_gemm_body<DM, DI, true>(g_y, W, g_h, g_h);
}

// ---------------- embed ----------------
__global__ void embed_kernel(const float* __restrict__ x,
                             const float* __restrict__ pos,
                             const float* __restrict__ We,
                             const float* __restrict__ be) {
    int row = blockIdx.x;
    int j   = threadIdx.x;
    int l   = row & (L_-1);
    float x0 = x[row*2+0], x1 = x[row*2+1];
    g_h[(size_t)row*DM + j]       = x0*We[j] + x1*We[128+j] + be[j];
    g_h[(size_t)row*DM + 128 + j] = pos[l*128 + j];
}

// ---------------- rmsnorm ----------------
__global__ void __launch_bounds__(256) rmsnorm_kernel(const float* __restrict__ w) {
    int row = blockIdx.x, tid = threadIdx.x;
    float v = g_h[(size_t)row*DM + tid];
    float ss = v*v;
    #pragma unroll
    for (int o = 16; o > 0; o >>= 1) ss += __shfl_xor_sync(0xffffffffu, ss, o);
    __shared__ float red[8];
    if ((tid & 31) == 0) red[tid >> 5] = ss;
    __syncthreads();
    float tot = 0.f;
    #pragma unroll
    for (int i = 0; i < 8; i++) tot += red[i];
    float scale = rsqrtf(tot * (1.f/DM) + 1e-5f);
    g_xn[(size_t)row*DM + tid] = v * scale * w[tid];
}

// ---------------- causal depthwise conv (K=4) + silu ----------------
__global__ void __launch_bounds__(256) conv_silu_kernel(const float* __restrict__ cw,
                                                        const float* __restrict__ cb) {
    int idx = blockIdx.x*256 + threadIdx.x;
    int d   = idx & (DI-1);
    int row = idx >> 9;
    int l   = row & (L_-1);
    float c0 = cw[d*KC+0], c1 = cw[d*KC+1], c2 = cw[d*KC+2], c3 = cw[d*KC+3];
    const float* base = g_hidgate + (size_t)row*(2*DI) + d;
    float acc = cb[d];
    if (l >= 3) acc = fmaf(base[-3*2*DI], c0, acc);
    if (l >= 2) acc = fmaf(base[-2*2*DI], c1, acc);
    if (l >= 1) acc = fmaf(base[-1*2*DI], c2, acc);
    acc = fmaf(base[0], c3, acc);
    g_hid[idx] = acc / (1.f + __expf(-acc));
}

// ---------------- delta = softplus(dt @ Wdt + b_dt) (R4 style, parallel) --------
__global__ void __launch_bounds__(512) delta_kernel(const float* __restrict__ Wdt,
                                                    const float* __restrict__ bdt) {
    int row = blockIdx.x, d = threadIdx.x;
    __shared__ float dt[DTR];
    if (d < DTR) dt[d] = g_sp[row*48 + d];
    __syncthreads();
    float acc = bdt[d];
    #pragma unroll
    for (int r = 0; r < DTR; r++) acc = fmaf(dt[r], Wdt[r*DI + d], acc);
    g_delta[(size_t)row*DI + d] = (acc > 20.f) ? acc : log1pf(__expf(acc));
}

// ---------------- scan pass 1: per-segment summaries (no shfl) ----------------
// block = (b, dblk, s); threads: n = tid&15, dl = tid>>4
#define CH 16
__global__ void __launch_bounds__(256) scan_seg1(const float* __restrict__ Alog) {
    const int s    = blockIdx.x & (SEG-1);
    const int dblk = (blockIdx.x >> 3) & 31;
    const int b    = blockIdx.x >> 8;
    const int tid  = threadIdx.x;
    const int n    = tid & 15;
    const int dl   = tid >> 4;
    const int d    = dblk*16 + dl;
    const float A  = -__expf(Alog[d*NS + n]);
    float h = 0.f, P = 1.f;
    __shared__ float s_delta[CH][16], s_hid[CH][16], s_B[CH][16];
    const int tbase = b*L_ + s*SEGLEN;
    for (int t0 = 0; t0 < SEGLEN; t0 += CH) {
        __syncthreads();
        {
            int tt = tid >> 4, c = tid & 15;
            int row = tbase + t0 + tt;
            s_delta[tt][c] = g_delta[(size_t)row*DI + dblk*16 + c];
            s_hid[tt][c]   = g_hid  [(size_t)row*DI + dblk*16 + c];
            s_B[tt][c]     = g_sp[row*48 + DTR + c];
        }
        __syncthreads();
        #pragma unroll
        for (int tt = 0; tt < CH; tt++) {
            float de  = s_delta[tt][dl];
            float dA  = __expf(de * A);
            float dBu = de * s_B[tt][n] * s_hid[tt][dl];
            h = fmaf(dA, h, dBu);
            P *= dA;
        }
    }
    int idx = ((b*32 + dblk)*SEG + s)*256 + tid;
    g_segP[idx] = P;
    g_segH[idx] = h;
}

// ---------------- scan pass 2: replay with carried-in state, emit y -----------
__global__ void __launch_bounds__(256) scan_seg2(const float* __restrict__ Alog,
                                                 const float* __restrict__ Dsk) {
    const int s    = blockIdx.x & (SEG-1);
    const int dblk = (blockIdx.x >> 3) & 31;
    const int b    = blockIdx.x >> 8;
    const int tid  = threadIdx.x;
    const int n    = tid & 15;
    const int dl   = tid >> 4;
    const int d    = dblk*16 + dl;
    const float A  = -__expf(Alog[d*NS + n]);
    const float Dskip = Dsk[d];

    // incoming state: combine earlier segments (linear recurrence composition)
    float h = 0.f;
    {
        const int base = (b*32 + dblk)*SEG;
        for (int ss = 0; ss < s; ss++) {
            int idx = (base + ss)*256 + tid;
            h = fmaf(g_segP[idx], h, g_segH[idx]);
        }
    }

    __shared__ float s_delta[CH][16], s_hid[CH][16], s_B[CH][16],
                     s_C[CH][16], s_gate[CH][16], s_y[CH][16];
    const int tbase = b*L_ + s*SEGLEN;
    for (int t0 = 0; t0 < SEGLEN; t0 += CH) {
        __syncthreads();
        {
            int tt = tid >> 4, c = tid & 15;
            int row = tbase + t0 + tt;
            s_delta[tt][c] = g_delta[(size_t)row*DI + dblk*16 + c];
            s_hid[tt][c]   = g_hid  [(size_t)row*DI + dblk*16 + c];
            s_B[tt][c]     = g_sp[row*48 + DTR + c];
            s_C[tt][c]     = g_sp[row*48 + DTR + NS + c];
            s_gate[tt][c]  = g_hidgate[(size_t)row*(2*DI) + DI + dblk*16 + c];
        }
        __syncthreads();
        #pragma unroll
        for (int tt = 0; tt < CH; tt++) {
            float de  = s_delta[tt][dl];
            float dA  = __expf(de * A);
            float dBu = de * s_B[tt][n] * s_hid[tt][dl];
            h = fmaf(dA, h, dBu);
            float contrib = h * s_C[tt][n];
            contrib += __shfl_xor_sync(0xffffffffu, contrib, 1);
            contrib += __shfl_xor_sync(0xffffffffu, contrib, 2);
            contrib += __shfl_xor_sync(0xffffffffu, contrib, 4);
            contrib += __shfl_xor_sync(0xffffffffu, contrib, 8);
            if (n == 0) {
                float yv = contrib + s_hid[tt][dl]*Dskip;
                float g  = s_gate[tt][dl];
                s_y[tt][dl] = yv * g / (1.f + __expf(-g));
            }
        }
        __syncthreads();
        {
            int tt = tid >> 4, c = tid & 15;
            int row = tbase + t0 + tt;
            g_y[(size_t)row*DI + dblk*16 + c] = s_y[tt][c];
        }
    }
}

// ---------------- output head ----------------
__global__ void __launch_bounds__(256) head_kernel(const float* __restrict__ Wa,
                                                   const float* __restrict__ ba,
                                                   const float* __restrict__ Wp,
                                                   const float* __restrict__ bp,
                                                   float* __restrict__ out) {
    int row = blockIdx.x, tid = threadIdx.x;
    float v  = g_h[(size_t)row*DM + tid];
    float pa = v * Wa[tid];
    float pp = v * Wp[tid];
    #pragma unroll
    for (int o = 16; o > 0; o >>= 1) {
        pa += __shfl_xor_sync(0xffffffffu, pa, o);
        pp += __shfl_xor_sync(0xffffffffu, pp, o);
    }
    __shared__ float ra[8], rp[8];
    if ((tid & 31) == 0) { ra[tid>>5] = pa; rp[tid>>5] = pp; }
    __syncthreads();
    if (tid == 0) {
        float sa = 0.f, sp2 = 0.f;
        #pragma unroll
        for (int i = 0; i < 8; i++) { sa += ra[i]; sp2 += rp[i]; }
        out[row*2+0] = sa + ba[0];
        out[row*2+1] = tanhf(sp2 + bp[0]);
    }
}

// ---------------- launch ----------------
extern "C" void kernel_launch(void* const* d_in, const int* in_sizes, int n_in,
                              void* d_out, int out_size) {
    const float* x       = (const float*)d_in[0];
    const float* pos     = (const float*)d_in[1];
    const float* W_embed = (const float*)d_in[2];
    const float* b_embed = (const float*)d_in[3];
    const float* ln_w    = (const float*)d_in[4];
    const float* W_in    = (const float*)d_in[5];
    const float* conv_w  = (const float*)d_in[6];
    const float* conv_b  = (const float*)d_in[7];
    const float* W_x     = (const float*)d_in[8];
    const float* W_dt    = (const float*)d_in[9];
    const float* b_dt    = (const float*)d_in[10];
    const float* A_log   = (const float*)d_in[11];
    const float* D_skip  = (const float*)d_in[12];
    const float* W_out   = (const float*)d_in[13];
    const float* W_amp   = (const float*)d_in[14];
    const float* b_amp   = (const float*)d_in[15];
    const float* W_phase = (const float*)d_in[16];
    const float* b_phase = (const float*)d_in[17];

    embed_kernel<<<ROWS, 128>>>(x, pos, W_embed, b_embed);

    for (int i = 0; i < NL; i++) {
        rmsnorm_kernel<<<ROWS, 256>>>(ln_w + (size_t)i*DM);
        gemm_in_k<<<dim3((2*DI)/64, ROWS/64), 256>>>(W_in + (size_t)i*DM*2*DI);
        conv_silu_kernel<<<(ROWS*DI)/256, 256>>>(conv_w + (size_t)i*DI*KC,
                                                 conv_b + (size_t)i*DI);
        gemm_x_k<<<dim3(1, ROWS/64), 256>>>(W_x + (size_t)i*DI*48);
        delta_kernel<<<ROWS, DI>>>(W_dt + (size_t)i*DTR*DI, b_dt + (size_t)i*DI);
        scan_seg1<<<B_*32*SEG, 256>>>(A_log + (size_t)i*DI*NS);
        scan_seg2<<<B_*32*SEG, 256>>>(A_log + (size_t)i*DI*NS,
                                      D_skip + (size_t)i*DI);
        gemm_out_k<<<dim3(DM/64, ROWS/64), 256>>>(W_out + (size_t)i*DI*DM);
    }

    head_kernel<<<ROWS, 256>>>(W_amp, b_amp, W_phase, b_phase, (float*)d_out);
}

// round 13
// speedup vs baseline: 1.5501x; 1.0045x over previous
#include <cuda_runtime.h>
#include <math.h>
#include <stdint.h>

#define B_   4
#define L_   1024
#define DM   256
#define DI   512
#define NS   16
#define DTR  16
#define KC   4
#define NL   8
#define ROWS (B_*L_)
#define SEG  8
#define SEGLEN (L_/SEG)   // 128

// ---------------- static scratch (no allocs allowed) ----------------
__device__ float g_h[ROWS*DM];        // residual stream
__device__ float g_xn[ROWS*DM];       // rmsnorm output
__device__ float g_hidgate[ROWS*2*DI];// in-proj output: [hid | gate]
__device__ float g_hid[ROWS*DI];      // post conv+silu
__device__ float g_sp[ROWS*48];       // [dt(16) | B(16) | C(16)]
__device__ float g_y[ROWS*DI];        // scan output (gated)
__device__ float g_segP[B_*32*SEG*256];  // per-segment prod(dA) per (d,n)
__device__ float g_segH[B_*32*SEG*256];  // per-segment local final h per (d,n)

// ---------------- tf32 helpers (identical to R11/R12) ----------------
__device__ __forceinline__ uint32_t f2tf32(float x) {
    uint32_t r;
    asm("cvt.rna.tf32.f32 %0, %1;" : "=r"(r) : "f"(x));
    return r;
}
__device__ __forceinline__ void split_tf32(float x, uint32_t& hi, uint32_t& lo) {
    hi = f2tf32(x);
    float hif = __uint_as_float(hi);
    lo = f2tf32(x - hif);
}
__device__ __forceinline__ void mma_tf32(float& c0, float& c1, float& c2, float& c3,
                                         uint32_t a0, uint32_t a1, uint32_t a2, uint32_t a3,
                                         uint32_t b0, uint32_t b1) {
    asm volatile(
        "mma.sync.aligned.m16n8k8.row.col.f32.tf32.tf32.f32 "
        "{%0,%1,%2,%3}, {%4,%5,%6,%7}, {%8,%9}, {%0,%1,%2,%3};"
        : "+f"(c0), "+f"(c1), "+f"(c2), "+f"(c3)
        : "r"(a0), "r"(a1), "r"(a2), "r"(a3), "r"(b0), "r"(b1));
}

// ================= tf32-split GEMM — identical to R11/R12 (passed) =================
template<int N_, int K_, bool RES>
__device__ __forceinline__ void mma_gemm_body(const float* __restrict__ A,
                                              const float* __restrict__ Bw,
                                              float* C, const float* Res) {
    __shared__ uint32_t Ash[64][36], Asl[64][36];
    __shared__ uint32_t Bsh[32][72], Bsl[32][72];
    const int tid  = threadIdx.x;
    const int lane = tid & 31;
    const int warp = tid >> 5;
    const int wr   = warp & 3;
    const int wc   = warp >> 2;
    const int g    = lane >> 2;
    const int t    = lane & 3;
    const int row0 = blockIdx.y * 64;
    const int col0 = blockIdx.x * 64;

    float acc[4][4];
    #pragma unroll
    for (int nt = 0; nt < 4; nt++)
        #pragma unroll
        for (int q = 0; q < 4; q++) acc[nt][q] = 0.f;

    for (int k0 = 0; k0 < K_; k0 += 32) {
        #pragma unroll
        for (int it = 0; it < 2; it++) {
            int idx = tid + it*256;
            int r = idx >> 3, k4 = idx & 7;
            float4 v = *reinterpret_cast<const float4*>(
                A + (size_t)(row0 + r)*K_ + k0 + k4*4);
            uint32_t h0,l0,h1,l1,h2,l2,h3,l3;
            split_tf32(v.x, h0, l0);
            split_tf32(v.y, h1, l1);
            split_tf32(v.z, h2, l2);
            split_tf32(v.w, h3, l3);
            Ash[r][k4*4+0] = h0; Asl[r][k4*4+0] = l0;
            Ash[r][k4*4+1] = h1; Asl[r][k4*4+1] = l1;
            Ash[r][k4*4+2] = h2; Asl[r][k4*4+2] = l2;
            Ash[r][k4*4+3] = h3; Asl[r][k4*4+3] = l3;
        }
        #pragma unroll
        for (int it = 0; it < 2; it++) {
            int idx = tid + it*256;
            int k = idx >> 4, n4 = idx & 15;
            int gn = col0 + n4*4;
            float4 v;
            if ((N_ & 63) == 0 || gn + 3 < N_)
                v = *reinterpret_cast<const float4*>(Bw + (size_t)(k0 + k)*N_ + gn);
            else
                v = make_float4(0.f, 0.f, 0.f, 0.f);
            uint32_t h0,l0,h1,l1,h2,l2,h3,l3;
            split_tf32(v.x, h0, l0);
            split_tf32(v.y, h1, l1);
            split_tf32(v.z, h2, l2);
            split_tf32(v.w, h3, l3);
            Bsh[k][n4*4+0] = h0; Bsl[k][n4*4+0] = l0;
            Bsh[k][n4*4+1] = h1; Bsl[k][n4*4+1] = l1;
            Bsh[k][n4*4+2] = h2; Bsl[k][n4*4+2] = l2;
            Bsh[k][n4*4+3] = h3; Bsl[k][n4*4+3] = l3;
        }
        __syncthreads();

        #pragma unroll
        for (int ks = 0; ks < 4; ks++) {
            const int rb = wr*16 + g;
            const int kk = ks*8 + t;
            uint32_t ah[4], al[4];
            ah[0] = Ash[rb    ][kk    ];  al[0] = Asl[rb    ][kk    ];
            ah[1] = Ash[rb + 8][kk    ];  al[1] = Asl[rb + 8][kk    ];
            ah[2] = Ash[rb    ][kk + 4];  al[2] = Asl[rb    ][kk + 4];
            ah[3] = Ash[rb + 8][kk + 4];  al[3] = Asl[rb + 8][kk + 4];
            #pragma unroll
            for (int nt = 0; nt < 4; nt++) {
                const int cb = wc*32 + nt*8 + g;
                uint32_t bh0 = Bsh[ks*8 + t    ][cb];
                uint32_t bh1 = Bsh[ks*8 + t + 4][cb];
                uint32_t bl0 = Bsl[ks*8 + t    ][cb];
                uint32_t bl1 = Bsl[ks*8 + t + 4][cb];
                mma_tf32(acc[nt][0], acc[nt][1], acc[nt][2], acc[nt][3],
                         ah[0], ah[1], ah[2], ah[3], bh0, bh1);
                mma_tf32(acc[nt][0], acc[nt][1], acc[nt][2], acc[nt][3],
                         ah[0], ah[1], ah[2], ah[3], bl0, bl1);
                mma_tf32(acc[nt][0], acc[nt][1], acc[nt][2], acc[nt][3],
                         al[0], al[1], al[2], al[3], bh0, bh1);
            }
        }
        __syncthreads();
    }

    const int r0 = row0 + wr*16 + g;
    #pragma unroll
    for (int nt = 0; nt < 4; nt++) {
        const int cbase = col0 + wc*32 + nt*8 + 2*t;
        #pragma unroll
        for (int h = 0; h < 2; h++) {
            int gm = r0 + h*8;
            #pragma unroll
            for (int q = 0; q < 2; q++) {
                int gn = cbase + q;
                if ((N_ & 63) == 0 || gn < N_) {
                    float v = acc[nt][h*2 + q];
                    if (RES) v += Res[(size_t)gm*N_ + gn];
                    C[(size_t)gm*N_ + gn] = v;
                }
            }
        }
    }
}

__global__ void __launch_bounds__(256) gemm_in_k(const float* __restrict__ W) {
    mma_gemm_body<2*DI, DM, false>(g_xn, W, g_hidgate, nullptr);
}
__global__ void __launch_bounds__(256) gemm_x_k(const float* __restrict__ W) {
    mma_gemm_body<48, DI, false>(g_hid, W, g_sp, nullptr);
}
__global__ void __launch_bounds__(256) gemm_out_k(const float* __restrict__ W) {
    mma_gemm_body<DM, DI, true>(g_y, W, g_h, g_h);
}

// ---------------- embed ----------------
__global__ void embed_kernel(const float* __restrict__ x,
                             const float* __restrict__ pos,
                             const float* __restrict__ We,
                             const float* __restrict__ be) {
    int row = blockIdx.x;
    int j   = threadIdx.x;
    int l   = row & (L_-1);
    float x0 = x[row*2+0], x1 = x[row*2+1];
    g_h[(size_t)row*DM + j]       = x0*We[j] + x1*We[128+j] + be[j];
    g_h[(size_t)row*DM + 128 + j] = pos[l*128 + j];
}

// ---------------- rmsnorm: warp-per-row, float4 ----------------
__global__ void __launch_bounds__(256) rmsnorm_kernel(const float* __restrict__ w) {
    const int warp = threadIdx.x >> 5, lane = threadIdx.x & 31;
    const int row  = blockIdx.x * 8 + warp;
    const float* src = g_h + (size_t)row * DM;
    float4 v0 = *reinterpret_cast<const float4*>(src + lane * 4);
    float4 v1 = *reinterpret_cast<const float4*>(src + 128 + lane * 4);
    float ss = v0.x*v0.x + v0.y*v0.y + v0.z*v0.z + v0.w*v0.w
             + v1.x*v1.x + v1.y*v1.y + v1.z*v1.z + v1.w*v1.w;
    #pragma unroll
    for (int o = 16; o > 0; o >>= 1) ss += __shfl_xor_sync(0xffffffffu, ss, o);
    const float scale = rsqrtf(ss * (1.f/DM) + 1e-5f);
    float4 w0 = *reinterpret_cast<const float4*>(w + lane * 4);
    float4 w1 = *reinterpret_cast<const float4*>(w + 128 + lane * 4);
    float4 o0 = make_float4(v0.x*scale*w0.x, v0.y*scale*w0.y,
                            v0.z*scale*w0.z, v0.w*scale*w0.w);
    float4 o1 = make_float4(v1.x*scale*w1.x, v1.y*scale*w1.y,
                            v1.z*scale*w1.z, v1.w*scale*w1.w);
    float* dst = g_xn + (size_t)row * DM;
    *reinterpret_cast<float4*>(dst + lane * 4)       = o0;
    *reinterpret_cast<float4*>(dst + 128 + lane * 4) = o1;
}

// ---------------- causal depthwise conv (K=4) + silu, float4 ----------------
__global__ void __launch_bounds__(256) conv_silu_kernel(const float* __restrict__ cw,
                                                        const float* __restrict__ cb) {
    int idx  = blockIdx.x*256 + threadIdx.x;     // over ROWS*(DI/4)
    int d    = (idx & 127) * 4;
    int row  = idx >> 7;
    int l    = row & (L_-1);
    const float* base = g_hidgate + (size_t)row*(2*DI) + d;
    float4 w0 = *reinterpret_cast<const float4*>(cw + (d+0)*KC);
    float4 w1 = *reinterpret_cast<const float4*>(cw + (d+1)*KC);
    float4 w2 = *reinterpret_cast<const float4*>(cw + (d+2)*KC);
    float4 w3 = *reinterpret_cast<const float4*>(cw + (d+3)*KC);
    float4 bias = *reinterpret_cast<const float4*>(cb + d);
    const float4 zero = make_float4(0.f, 0.f, 0.f, 0.f);
    float4 x3 = (l >= 3) ? *reinterpret_cast<const float4*>(base - 3*2*DI) : zero;
    float4 x2 = (l >= 2) ? *reinterpret_cast<const float4*>(base - 2*2*DI) : zero;
    float4 x1 = (l >= 1) ? *reinterpret_cast<const float4*>(base - 1*2*DI) : zero;
    float4 x0 = *reinterpret_cast<const float4*>(base);
    float4 acc;
    acc.x = fmaf(x0.x, w0.w, fmaf(x1.x, w0.z, fmaf(x2.x, w0.y, fmaf(x3.x, w0.x, bias.x))));
    acc.y = fmaf(x0.y, w1.w, fmaf(x1.y, w1.z, fmaf(x2.y, w1.y, fmaf(x3.y, w1.x, bias.y))));
    acc.z = fmaf(x0.z, w2.w, fmaf(x1.z, w2.z, fmaf(x2.z, w2.y, fmaf(x3.z, w2.x, bias.z))));
    acc.w = fmaf(x0.w, w3.w, fmaf(x1.w, w3.z, fmaf(x2.w, w3.y, fmaf(x3.w, w3.x, bias.w))));
    float4 r;
    r.x = acc.x / (1.f + __expf(-acc.x));
    r.y = acc.y / (1.f + __expf(-acc.y));
    r.z = acc.z / (1.f + __expf(-acc.z));
    r.w = acc.w / (1.f + __expf(-acc.w));
    *reinterpret_cast<float4*>(g_hid + (size_t)row*DI + d) = r;
}

// ---------------- scan pass 1: per-segment summaries, delta fused ----------------
#define CH 16
__global__ void __launch_bounds__(256) scan_seg1(const float* __restrict__ Alog,
                                                 const float* __restrict__ Wdt,
                                                 const float* __restrict__ bdt) {
    const int s    = blockIdx.x & (SEG-1);
    const int dblk = (blockIdx.x >> 3) & 31;
    const int b    = blockIdx.x >> 8;
    const int tid  = threadIdx.x;
    const int n    = tid & 15;
    const int dl   = tid >> 4;
    const int d    = dblk*16 + dl;
    const float A  = -__expf(Alog[d*NS + n]);
    float h = 0.f, P = 1.f;
    __shared__ float s_Wdt[DTR][17], s_bdt[16];
    __shared__ float s_dt[CH][16], s_delta[CH][16], s_hid[CH][16], s_B[CH][16];
    {
        int r = tid >> 4, c = tid & 15;
        s_Wdt[r][c] = Wdt[r*DI + dblk*16 + c];
        if (tid < 16) s_bdt[tid] = bdt[dblk*16 + tid];
    }
    __syncthreads();
    const int tbase = b*L_ + s*SEGLEN;
    for (int t0 = 0; t0 < SEGLEN; t0 += CH) {
        __syncthreads();
        {
            int tt = tid >> 4, c = tid & 15;
            int row = tbase + t0 + tt;
            s_dt[tt][c]  = g_sp[row*48 + c];
            s_hid[tt][c] = g_hid[(size_t)row*DI + dblk*16 + c];
            s_B[tt][c]   = g_sp[row*48 + DTR + c];
        }
        __syncthreads();
        {
            int tt = tid >> 4, c = tid & 15;
            float acc = s_bdt[c];
            #pragma unroll
            for (int r = 0; r < DTR; r++) acc = fmaf(s_dt[tt][r], s_Wdt[r][c], acc);
            s_delta[tt][c] = (acc > 20.f) ? acc : log1pf(__expf(acc));
        }
        __syncthreads();
        #pragma unroll
        for (int tt = 0; tt < CH; tt++) {
            float de  = s_delta[tt][dl];
            float dA  = __expf(de * A);
            float dBu = de * s_B[tt][n] * s_hid[tt][dl];
            h = fmaf(dA, h, dBu);
            P *= dA;
        }
    }
    int idx = ((b*32 + dblk)*SEG + s)*256 + tid;
    g_segP[idx] = P;
    g_segH[idx] = h;
}

// ---------------- scan pass 2: replay with carried-in state, emit y -----------
__global__ void __launch_bounds__(256) scan_seg2(const float* __restrict__ Alog,
                                                 const float* __restrict__ Dsk,
                                                 const float* __restrict__ Wdt,
                                                 const float* __restrict__ bdt) {
    const int s    = blockIdx.x & (SEG-1);
    const int dblk = (blockIdx.x >> 3) & 31;
    const int b    = blockIdx.x >> 8;
    const int tid  = threadIdx.x;
    const int n    = tid & 15;
    const int dl   = tid >> 4;
    const int d    = dblk*16 + dl;
    const float A  = -__expf(Alog[d*NS + n]);
    const float Dskip = Dsk[d];

    // incoming state: prefetch summaries (parallel loads), then fold
    float h = 0.f;
    {
        const int base = (b*32 + dblk)*SEG;
        float Ps[SEG-1], Hs[SEG-1];
        #pragma unroll
        for (int ss = 0; ss < SEG-1; ss++) {
            if (ss < s) {
                int idx = (base + ss)*256 + tid;
                Ps[ss] = g_segP[idx];
                Hs[ss] = g_segH[idx];
            }
        }
        #pragma unroll
        for (int ss = 0; ss < SEG-1; ss++)
            if (ss < s) h = fmaf(Ps[ss], h, Hs[ss]);
    }

    __shared__ float s_Wdt[DTR][17], s_bdt[16];
    __shared__ float s_dt[CH][16], s_delta[CH][16], s_hid[CH][16], s_B[CH][16],
                     s_C[CH][16], s_gate[CH][16], s_y[CH][16];
    {
        int r = tid >> 4, c = tid & 15;
        s_Wdt[r][c] = Wdt[r*DI + dblk*16 + c];
        if (tid < 16) s_bdt[tid] = bdt[dblk*16 + tid];
    }
    __syncthreads();
    const int tbase = b*L_ + s*SEGLEN;
    for (int t0 = 0; t0 < SEGLEN; t0 += CH) {
        __syncthreads();
        {
            int tt = tid >> 4, c = tid & 15;
            int row = tbase + t0 + tt;
            s_dt[tt][c]   = g_sp[row*48 + c];
            s_hid[tt][c]  = g_hid[(size_t)row*DI + dblk*16 + c];
            s_B[tt][c]    = g_sp[row*48 + DTR + c];
            s_C[tt][c]    = g_sp[row*48 + DTR + NS + c];
            s_gate[tt][c] = g_hidgate[(size_t)row*(2*DI) + DI + dblk*16 + c];
        }
        __syncthreads();
        {
            int tt = tid >> 4, c = tid & 15;
            float acc = s_bdt[c];
            #pragma unroll
            for (int r = 0; r < DTR; r++) acc = fmaf(s_dt[tt][r], s_Wdt[r][c], acc);
            s_delta[tt][c] = (acc > 20.f) ? acc : log1pf(__expf(acc));
        }
        __syncthreads();
        #pragma unroll
        for (int tt = 0; tt < CH; tt++) {
            float de  = s_delta[tt][dl];
            float dA  = __expf(de * A);
            float dBu = de * s_B[tt][n] * s_hid[tt][dl];
            h = fmaf(dA, h, dBu);
            float contrib = h * s_C[tt][n];
            contrib += __shfl_xor_sync(0xffffffffu, contrib, 1);
            contrib += __shfl_xor_sync(0xffffffffu, contrib, 2);
            contrib += __shfl_xor_sync(0xffffffffu, contrib, 4);
            contrib += __shfl_xor_sync(0xffffffffu, contrib, 8);
            if (n == 0) {
                float yv = contrib + s_hid[tt][dl]*Dskip;
                float g  = s_gate[tt][dl];
                s_y[tt][dl] = yv * g / (1.f + __expf(-g));
            }
        }
        __syncthreads();
        {
            int tt = tid >> 4, c = tid & 15;
            int row = tbase + t0 + tt;
            g_y[(size_t)row*DI + dblk*16 + c] = s_y[tt][c];
        }
    }
}

// ---------------- output head ----------------
__global__ void __launch_bounds__(256) head_kernel(const float* __restrict__ Wa,
                                                   const float* __restrict__ ba,
                                                   const float* __restrict__ Wp,
                                                   const float* __restrict__ bp,
                                                   float* __restrict__ out) {
    int row = blockIdx.x, tid = threadIdx.x;
    float v  = g_h[(size_t)row*DM + tid];
    float pa = v * Wa[tid];
    float pp = v * Wp[tid];
    #pragma unroll
    for (int o = 16; o > 0; o >>= 1) {
        pa += __shfl_xor_sync(0xffffffffu, pa, o);
        pp += __shfl_xor_sync(0xffffffffu, pp, o);
    }
    __shared__ float ra[8], rp[8];
    if ((tid & 31) == 0) { ra[tid>>5] = pa; rp[tid>>5] = pp; }
    __syncthreads();
    if (tid == 0) {
        float sa = 0.f, sp2 = 0.f;
        #pragma unroll
        for (int i = 0; i < 8; i++) { sa += ra[i]; sp2 += rp[i]; }
        out[row*2+0] = sa + ba[0];
        out[row*2+1] = tanhf(sp2 + bp[0]);
    }
}

// ---------------- launch ----------------
extern "C" void kernel_launch(void* const* d_in, const int* in_sizes, int n_in,
                              void* d_out, int out_size) {
    const float* x       = (const float*)d_in[0];
    const float* pos     = (const float*)d_in[1];
    const float* W_embed = (const float*)d_in[2];
    const float* b_embed = (const float*)d_in[3];
    const float* ln_w    = (const float*)d_in[4];
    const float* W_in    = (const float*)d_in[5];
    const float* conv_w  = (const float*)d_in[6];
    const float* conv_b  = (const float*)d_in[7];
    const float* W_x     = (const float*)d_in[8];
    const float* W_dt    = (const float*)d_in[9];
    const float* b_dt    = (const float*)d_in[10];
    const float* A_log   = (const float*)d_in[11];
    const float* D_skip  = (const float*)d_in[12];
    const float* W_out   = (const float*)d_in[13];
    const float* W_amp   = (const float*)d_in[14];
    const float* b_amp   = (const float*)d_in[15];
    const float* W_phase = (const float*)d_in[16];
    const float* b_phase = (const float*)d_in[17];

    embed_kernel<<<ROWS, 128>>>(x, pos, W_embed, b_embed);

    for (int i = 0; i < NL; i++) {
        rmsnorm_kernel<<<ROWS/8, 256>>>(ln_w + (size_t)i*DM);
        gemm_in_k<<<dim3((2*DI)/64, ROWS/64), 256>>>(W_in + (size_t)i*DM*2*DI);
        conv_silu_kernel<<<(ROWS*DI/4)/256, 256>>>(conv_w + (size_t)i*DI*KC,
                                                   conv_b + (size_t)i*DI);
        gemm_x_k<<<dim3(1, ROWS/64), 256>>>(W_x + (size_t)i*DI*48);
        scan_seg1<<<B_*32*SEG, 256>>>(A_log + (size_t)i*DI*NS,
                                      W_dt + (size_t)i*DTR*DI,
                                      b_dt + (size_t)i*DI);
        scan_seg2<<<B_*32*SEG, 256>>>(A_log + (size_t)i*DI*NS,
                                      D_skip + (size_t)i*DI,
                                      W_dt + (size_t)i*DTR*DI,
                                      b_dt + (size_t)i*DI);
        gemm_out_k<<<dim3(DM/64, ROWS/64), 256>>>(W_out + (size_t)i*DI*DM);
    }

    head_kernel<<<ROWS, 256>>>(W_amp, b_amp, W_phase, b_phase, (float*)d_out);
}

// round 14
// speedup vs baseline: 1.5905x; 1.0260x over previous
#include <cuda_runtime.h>
#include <cuda_fp16.h>
#include <math.h>
#include <stdint.h>

#define B_   4
#define L_   1024
#define DM   256
#define DI   512
#define NS   16
#define DTR  16
#define KC   4
#define NL   8
#define ROWS (B_*L_)
#define SEG  8
#define SEGLEN (L_/SEG)   // 128

// ---------------- static scratch (no allocs allowed) ----------------
__device__ float g_h[ROWS*DM];        // residual stream
__device__ float g_xn[ROWS*DM];       // rmsnorm output
__device__ float g_hidgate[ROWS*2*DI];// in-proj output: [hid | gate]
__device__ float g_hid[ROWS*DI];      // post conv+silu
__device__ float g_sp[ROWS*48];       // [dt(16) | B(16) | C(16)]
__device__ float g_y[ROWS*DI];        // scan output (gated)
__device__ float g_segP[B_*32*SEG*256];  // per-segment prod(dA) per (d,n)
__device__ float g_segH[B_*32*SEG*256];  // per-segment local final h per (d,n)

// ---------------- f16-split helpers ----------------
#define LO_SCALE    2048.0f
#define LO_UNSCALE  (1.0f/2048.0f)

__device__ __forceinline__ uint32_t pack_h2(float x, float y) {
    __half2 h = __floats2half2_rn(x, y);
    return *reinterpret_cast<uint32_t*>(&h);
}
// split x = hi + lo, lo pre-scaled by 2048 to stay in f16 normal range
__device__ __forceinline__ void split_f16(float x, float& hi, float& lo) {
    hi = __half2float(__float2half_rn(x));
    lo = (x - hi) * LO_SCALE;
}
__device__ __forceinline__ void mma_f16(float* c,
                                        uint32_t a0, uint32_t a1, uint32_t a2, uint32_t a3,
                                        uint32_t b0, uint32_t b1) {
    asm volatile(
        "mma.sync.aligned.m16n8k16.row.col.f32.f16.f16.f32 "
        "{%0,%1,%2,%3}, {%4,%5,%6,%7}, {%8,%9}, {%0,%1,%2,%3};"
        : "+f"(c[0]), "+f"(c[1]), "+f"(c[2]), "+f"(c[3])
        : "r"(a0), "r"(a1), "r"(a2), "r"(a3), "r"(b0), "r"(b1));
}

// ================= f16-split GEMM (3-term, scaled lo) =================
// C[M,N] = A[M,K] @ W[K,N] (+Res). 256 threads, 64x64 tile, m16n8k16.
// smem: f16x2 words, rows of 16 words padded to stride 20 (fragment reads conflict-free).
template<int N_, int K_, bool RES>
__device__ __forceinline__ void mma_gemm_body(const float* __restrict__ A,
                                              const float* __restrict__ Bw,
                                              float* C, const float* Res) {
    __shared__ uint32_t Ash[64][20], Asl[64][20];
    __shared__ uint32_t Bsh[64][20], Bsl[64][20];
    const int tid  = threadIdx.x;
    const int lane = tid & 31;
    const int warp = tid >> 5;
    const int wr   = warp & 3;     // 16 rows each
    const int wc   = warp >> 2;    // 32 cols each
    const int g    = lane >> 2;
    const int t    = lane & 3;
    const int row0 = blockIdx.y * 64;
    const int col0 = blockIdx.x * 64;

    float acc [4][4];   // hi*hi
    float acc2[4][4];   // cross terms (scaled by 2048)
    #pragma unroll
    for (int nt = 0; nt < 4; nt++)
        #pragma unroll
        for (int q = 0; q < 4; q++) { acc[nt][q] = 0.f; acc2[nt][q] = 0.f; }

    for (int k0 = 0; k0 < K_; k0 += 32) {
        // ---- stage A: 64 rows x 32 k; 512 float4, 2/thread ----
        #pragma unroll
        for (int it = 0; it < 2; it++) {
            int idx = tid + it*256;
            int r = idx >> 3, k4 = idx & 7;
            float4 v = *reinterpret_cast<const float4*>(
                A + (size_t)(row0 + r)*K_ + k0 + k4*4);
            float hx,lx,hy,ly,hz,lz,hw,lw;
            split_f16(v.x, hx, lx);
            split_f16(v.y, hy, ly);
            split_f16(v.z, hz, lz);
            split_f16(v.w, hw, lw);
            Ash[r][k4*2    ] = pack_h2(hx, hy);
            Ash[r][k4*2 + 1] = pack_h2(hz, hw);
            Asl[r][k4*2    ] = pack_h2(lx, ly);
            Asl[r][k4*2 + 1] = pack_h2(lz, lw);
        }
        // ---- stage B as [n][kpair]: 512 groups (kp, n-pair), 2/thread ----
        #pragma unroll
        for (int it = 0; it < 2; it++) {
            int idx = tid + it*256;
            int kp = idx & 15, np = idx >> 4;     // kp 0..15, np 0..31
            int gn = col0 + np*2;
            float2 v0, v1;
            if ((N_ & 63) == 0 || gn < N_) {
                v0 = *reinterpret_cast<const float2*>(Bw + (size_t)(k0 + 2*kp    )*N_ + gn);
                v1 = *reinterpret_cast<const float2*>(Bw + (size_t)(k0 + 2*kp + 1)*N_ + gn);
            } else {
                v0 = make_float2(0.f, 0.f);
                v1 = v0;
            }
            float h00,l00,h10,l10,h01,l01,h11,l11;
            split_f16(v0.x, h00, l00);   // (k even, n)
            split_f16(v1.x, h10, l10);   // (k odd,  n)
            split_f16(v0.y, h01, l01);   // (k even, n+1)
            split_f16(v1.y, h11, l11);   // (k odd,  n+1)
            Bsh[np*2    ][kp] = pack_h2(h00, h10);
            Bsh[np*2 + 1][kp] = pack_h2(h01, h11);
            Bsl[np*2    ][kp] = pack_h2(l00, l10);
            Bsl[np*2 + 1][kp] = pack_h2(l01, l11);
        }
        __syncthreads();

        #pragma unroll
        for (int ks = 0; ks < 2; ks++) {           // two k16 steps per chunk
            const int rb = wr*16 + g;
            const int kb = ks*8 + t;
            uint32_t ah0 = Ash[rb    ][kb    ], ah1 = Ash[rb + 8][kb    ];
            uint32_t ah2 = Ash[rb    ][kb + 4], ah3 = Ash[rb + 8][kb + 4];
            uint32_t al0 = Asl[rb    ][kb    ], al1 = Asl[rb + 8][kb    ];
            uint32_t al2 = Asl[rb    ][kb + 4], al3 = Asl[rb + 8][kb + 4];
            #pragma unroll
            for (int nt = 0; nt < 4; nt++) {
                const int cb = wc*32 + nt*8 + g;
                uint32_t bh0 = Bsh[cb][kb], bh1 = Bsh[cb][kb + 4];
                uint32_t bl0 = Bsl[cb][kb], bl1 = Bsl[cb][kb + 4];
                mma_f16(acc [nt], ah0, ah1, ah2, ah3, bh0, bh1);
                mma_f16(acc2[nt], ah0, ah1, ah2, ah3, bl0, bl1);
                mma_f16(acc2[nt], al0, al1, al2, al3, bh0, bh1);
            }
        }
        __syncthreads();
    }

    // epilogue: c0:(r,2q) c1:(r,2q+1) c2/c3:(+8 rows); fold scaled cross terms
    const int r0 = row0 + wr*16 + g;
    #pragma unroll
    for (int nt = 0; nt < 4; nt++) {
        const int cbase = col0 + wc*32 + nt*8 + 2*t;
        #pragma unroll
        for (int h = 0; h < 2; h++) {
            int gm = r0 + h*8;
            #pragma unroll
            for (int q = 0; q < 2; q++) {
                int gn = cbase + q;
                if ((N_ & 63) == 0 || gn < N_) {
                    float v = fmaf(acc2[nt][h*2 + q], LO_UNSCALE, acc[nt][h*2 + q]);
                    if (RES) v += Res[(size_t)gm*N_ + gn];
                    C[(size_t)gm*N_ + gn] = v;
                }
            }
        }
    }
}

__global__ void __launch_bounds__(256) gemm_in_k(const float* __restrict__ W) {
    mma_gemm_body<2*DI, DM, false>(g_xn, W, g_hidgate, nullptr);
}
__global__ void __launch_bounds__(256) gemm_x_k(const float* __restrict__ W) {
    mma_gemm_body<48, DI, false>(g_hid, W, g_sp, nullptr);
}
__global__ void __launch_bounds__(256) gemm_out_k(const float* __restrict__ W) {
    mma_gemm_body<DM, DI, true>(g_y, W, g_h, g_h);
}

// ---------------- embed ----------------
__global__ void embed_kernel(const float* __restrict__ x,
                             const float* __restrict__ pos,
                             const float* __restrict__ We,
                             const float* __restrict__ be) {
    int row = blockIdx.x;
    int j   = threadIdx.x;
    int l   = row & (L_-1);
    float x0 = x[row*2+0], x1 = x[row*2+1];
    g_h[(size_t)row*DM + j]       = x0*We[j] + x1*We[128+j] + be[j];
    g_h[(size_t)row*DM + 128 + j] = pos[l*128 + j];
}

// ---------------- rmsnorm: warp-per-row, float4 ----------------
__global__ void __launch_bounds__(256) rmsnorm_kernel(const float* __restrict__ w) {
    const int warp = threadIdx.x >> 5, lane = threadIdx.x & 31;
    const int row  = blockIdx.x * 8 + warp;
    const float* src = g_h + (size_t)row * DM;
    float4 v0 = *reinterpret_cast<const float4*>(src + lane * 4);
    float4 v1 = *reinterpret_cast<const float4*>(src + 128 + lane * 4);
    float ss = v0.x*v0.x + v0.y*v0.y + v0.z*v0.z + v0.w*v0.w
             + v1.x*v1.x + v1.y*v1.y + v1.z*v1.z + v1.w*v1.w;
    #pragma unroll
    for (int o = 16; o > 0; o >>= 1) ss += __shfl_xor_sync(0xffffffffu, ss, o);
    const float scale = rsqrtf(ss * (1.f/DM) + 1e-5f);
    float4 w0 = *reinterpret_cast<const float4*>(w + lane * 4);
    float4 w1 = *reinterpret_cast<const float4*>(w + 128 + lane * 4);
    float4 o0 = make_float4(v0.x*scale*w0.x, v0.y*scale*w0.y,
                            v0.z*scale*w0.z, v0.w*scale*w0.w);
    float4 o1 = make_float4(v1.x*scale*w1.x, v1.y*scale*w1.y,
                            v1.z*scale*w1.z, v1.w*scale*w1.w);
    float* dst = g_xn + (size_t)row * DM;
    *reinterpret_cast<float4*>(dst + lane * 4)       = o0;
    *reinterpret_cast<float4*>(dst + 128 + lane * 4) = o1;
}

// ---------------- causal depthwise conv (K=4) + silu, float4 ----------------
__global__ void __launch_bounds__(256) conv_silu_kernel(const float* __restrict__ cw,
                                                        const float* __restrict__ cb) {
    int idx  = blockIdx.x*256 + threadIdx.x;     // over ROWS*(DI/4)
    int d    = (idx & 127) * 4;
    int row  = idx >> 7;
    int l    = row & (L_-1);
    const float* base = g_hidgate + (size_t)row*(2*DI) + d;
    float4 w0 = *reinterpret_cast<const float4*>(cw + (d+0)*KC);
    float4 w1 = *reinterpret_cast<const float4*>(cw + (d+1)*KC);
    float4 w2 = *reinterpret_cast<const float4*>(cw + (d+2)*KC);
    float4 w3 = *reinterpret_cast<const float4*>(cw + (d+3)*KC);
    float4 bias = *reinterpret_cast<const float4*>(cb + d);
    const float4 zero = make_float4(0.f, 0.f, 0.f, 0.f);
    float4 x3 = (l >= 3) ? *reinterpret_cast<const float4*>(base - 3*2*DI) : zero;
    float4 x2 = (l >= 2) ? *reinterpret_cast<const float4*>(base - 2*2*DI) : zero;
    float4 x1 = (l >= 1) ? *reinterpret_cast<const float4*>(base - 1*2*DI) : zero;
    float4 x0 = *reinterpret_cast<const float4*>(base);
    float4 acc;
    acc.x = fmaf(x0.x, w0.w, fmaf(x1.x, w0.z, fmaf(x2.x, w0.y, fmaf(x3.x, w0.x, bias.x))));
    acc.y = fmaf(x0.y, w1.w, fmaf(x1.y, w1.z, fmaf(x2.y, w1.y, fmaf(x3.y, w1.x, bias.y))));
    acc.z = fmaf(x0.z, w2.w, fmaf(x1.z, w2.z, fmaf(x2.z, w2.y, fmaf(x3.z, w2.x, bias.z))));
    acc.w = fmaf(x0.w, w3.w, fmaf(x1.w, w3.z, fmaf(x2.w, w3.y, fmaf(x3.w, w3.x, bias.w))));
    float4 r;
    r.x = acc.x / (1.f + __expf(-acc.x));
    r.y = acc.y / (1.f + __expf(-acc.y));
    r.z = acc.z / (1.f + __expf(-acc.z));
    r.w = acc.w / (1.f + __expf(-acc.w));
    *reinterpret_cast<float4*>(g_hid + (size_t)row*DI + d) = r;
}

// ---------------- scan pass 1: per-segment summaries, delta fused ----------------
#define CH 16
__global__ void __launch_bounds__(256) scan_seg1(const float* __restrict__ Alog,
                                                 const float* __restrict__ Wdt,
                                                 const float* __restrict__ bdt) {
    const int s    = blockIdx.x & (SEG-1);
    const int dblk = (blockIdx.x >> 3) & 31;
    const int b    = blockIdx.x >> 8;
    const int tid  = threadIdx.x;
    const int n    = tid & 15;
    const int dl   = tid >> 4;
    const int d    = dblk*16 + dl;
    const float A  = -__expf(Alog[d*NS + n]);
    float h = 0.f, P = 1.f;
    __shared__ float s_Wdt[DTR][17], s_bdt[16];
    __shared__ float s_dt[CH][16], s_delta[CH][16], s_hid[CH][16], s_B[CH][16];
    {
        int r = tid >> 4, c = tid & 15;
        s_Wdt[r][c] = Wdt[r*DI + dblk*16 + c];
        if (tid < 16) s_bdt[tid] = bdt[dblk*16 + tid];
    }
    __syncthreads();
    const int tbase = b*L_ + s*SEGLEN;
    for (int t0 = 0; t0 < SEGLEN; t0 += CH) {
        __syncthreads();
        {
            int tt = tid >> 4, c = tid & 15;
            int row = tbase + t0 + tt;
            s_dt[tt][c]  = g_sp[row*48 + c];
            s_hid[tt][c] = g_hid[(size_t)row*DI + dblk*16 + c];
            s_B[tt][c]   = g_sp[row*48 + DTR + c];
        }
        __syncthreads();
        {
            int tt = tid >> 4, c = tid & 15;
            float acc = s_bdt[c];
            #pragma unroll
            for (int r = 0; r < DTR; r++) acc = fmaf(s_dt[tt][r], s_Wdt[r][c], acc);
            s_delta[tt][c] = (acc > 20.f) ? acc : log1pf(__expf(acc));
        }
        __syncthreads();
        #pragma unroll
        for (int tt = 0; tt < CH; tt++) {
            float de  = s_delta[tt][dl];
            float dA  = __expf(de * A);
            float dBu = de * s_B[tt][n] * s_hid[tt][dl];
            h = fmaf(dA, h, dBu);
            P *= dA;
        }
    }
    int idx = ((b*32 + dblk)*SEG + s)*256 + tid;
    g_segP[idx] = P;
    g_segH[idx] = h;
}

// ---------------- scan pass 2: replay with carried-in state, emit y -----------
__global__ void __launch_bounds__(256) scan_seg2(const float* __restrict__ Alog,
                                                 const float* __restrict__ Dsk,
                                                 const float* __restrict__ Wdt,
                                                 const float* __restrict__ bdt) {
    const int s    = blockIdx.x & (SEG-1);
    const int dblk = (blockIdx.x >> 3) & 31;
    const int b    = blockIdx.x >> 8;
    const int tid  = threadIdx.x;
    const int n    = tid & 15;
    const int dl   = tid >> 4;
    const int d    = dblk*16 + dl;
    const float A  = -__expf(Alog[d*NS + n]);
    const float Dskip = Dsk[d];

    // incoming state: prefetch summaries (parallel loads), then fold
    float h = 0.f;
    {
        const int base = (b*32 + dblk)*SEG;
        float Ps[SEG-1], Hs[SEG-1];
        #pragma unroll
        for (int ss = 0; ss < SEG-1; ss++) {
            if (ss < s) {
                int idx = (base + ss)*256 + tid;
                Ps[ss] = g_segP[idx];
                Hs[ss] = g_segH[idx];
            }
        }
        #pragma unroll
        for (int ss = 0; ss < SEG-1; ss++)
            if (ss < s) h = fmaf(Ps[ss], h, Hs[ss]);
    }

    __shared__ float s_Wdt[DTR][17], s_bdt[16];
    __shared__ float s_dt[CH][16], s_delta[CH][16], s_hid[CH][16], s_B[CH][16],
                     s_C[CH][16], s_gate[CH][16], s_y[CH][16];
    {
        int r = tid >> 4, c = tid & 15;
        s_Wdt[r][c] = Wdt[r*DI + dblk*16 + c];
        if (tid < 16) s_bdt[tid] = bdt[dblk*16 + tid];
    }
    __syncthreads();
    const int tbase = b*L_ + s*SEGLEN;
    for (int t0 = 0; t0 < SEGLEN; t0 += CH) {
        __syncthreads();
        {
            int tt = tid >> 4, c = tid & 15;
            int row = tbase + t0 + tt;
            s_dt[tt][c]   = g_sp[row*48 + c];
            s_hid[tt][c]  = g_hid[(size_t)row*DI + dblk*16 + c];
            s_B[tt][c]    = g_sp[row*48 + DTR + c];
            s_C[tt][c]    = g_sp[row*48 + DTR + NS + c];
            s_gate[tt][c] = g_hidgate[(size_t)row*(2*DI) + DI + dblk*16 + c];
        }
        __syncthreads();
        {
            int tt = tid >> 4, c = tid & 15;
            float acc = s_bdt[c];
            #pragma unroll
            for (int r = 0; r < DTR; r++) acc = fmaf(s_dt[tt][r], s_Wdt[r][c], acc);
            s_delta[tt][c] = (acc > 20.f) ? acc : log1pf(__expf(acc));
        }
        __syncthreads();
        #pragma unroll
        for (int tt = 0; tt < CH; tt++) {
            float de  = s_delta[tt][dl];
            float dA  = __expf(de * A);
            float dBu = de * s_B[tt][n] * s_hid[tt][dl];
            h = fmaf(dA, h, dBu);
            float contrib = h * s_C[tt][n];
            contrib += __shfl_xor_sync(0xffffffffu, contrib, 1);
            contrib += __shfl_xor_sync(0xffffffffu, contrib, 2);
            contrib += __shfl_xor_sync(0xffffffffu, contrib, 4);
            contrib += __shfl_xor_sync(0xffffffffu, contrib, 8);
            if (n == 0) {
                float yv = contrib + s_hid[tt][dl]*Dskip;
                float g  = s_gate[tt][dl];
                s_y[tt][dl] = yv * g / (1.f + __expf(-g));
            }
        }
        __syncthreads();
        {
            int tt = tid >> 4, c = tid & 15;
            int row = tbase + t0 + tt;
            g_y[(size_t)row*DI + dblk*16 + c] = s_y[tt][c];
        }
    }
}

// ---------------- output head ----------------
__global__ void __launch_bounds__(256) head_kernel(const float* __restrict__ Wa,
                                                   const float* __restrict__ ba,
                                                   const float* __restrict__ Wp,
                                                   const float* __restrict__ bp,
                                                   float* __restrict__ out) {
    int row = blockIdx.x, tid = threadIdx.x;
    float v  = g_h[(size_t)row*DM + tid];
    float pa = v * Wa[tid];
    float pp = v * Wp[tid];
    #pragma unroll
    for (int o = 16; o > 0; o >>= 1) {
        pa += __shfl_xor_sync(0xffffffffu, pa, o);
        pp += __shfl_xor_sync(0xffffffffu, pp, o);
    }
    __shared__ float ra[8], rp[8];
    if ((tid & 31) == 0) { ra[tid>>5] = pa; rp[tid>>5] = pp; }
    __syncthreads();
    if (tid == 0) {
        float sa = 0.f, sp2 = 0.f;
        #pragma unroll
        for (int i = 0; i < 8; i++) { sa += ra[i]; sp2 += rp[i]; }
        out[row*2+0] = sa + ba[0];
        out[row*2+1] = tanhf(sp2 + bp[0]);
    }
}

// ---------------- launch ----------------
extern "C" void kernel_launch(void* const* d_in, const int* in_sizes, int n_in,
                              void* d_out, int out_size) {
    const float* x       = (const float*)d_in[0];
    const float* pos     = (const float*)d_in[1];
    const float* W_embed = (const float*)d_in[2];
    const float* b_embed = (const float*)d_in[3];
    const float* ln_w    = (const float*)d_in[4];
    const float* W_in    = (const float*)d_in[5];
    const float* conv_w  = (const float*)d_in[6];
    const float* conv_b  = (const float*)d_in[7];
    const float* W_x     = (const float*)d_in[8];
    const float* W_dt    = (const float*)d_in[9];
    const float* b_dt    = (const float*)d_in[10];
    const float* A_log   = (const float*)d_in[11];
    const float* D_skip  = (const float*)d_in[12];
    const float* W_out   = (const float*)d_in[13];
    const float* W_amp   = (const float*)d_in[14];
    const float* b_amp   = (const float*)d_in[15];
    const float* W_phase = (const float*)d_in[16];
    const float* b_phase = (const float*)d_in[17];

    embed_kernel<<<ROWS, 128>>>(x, pos, W_embed, b_embed);

    for (int i = 0; i < NL; i++) {
        rmsnorm_kernel<<<ROWS/8, 256>>>(ln_w + (size_t)i*DM);
        gemm_in_k<<<dim3((2*DI)/64, ROWS/64), 256>>>(W_in + (size_t)i*DM*2*DI);
        conv_silu_kernel<<<(ROWS*DI/4)/256, 256>>>(conv_w + (size_t)i*DI*KC,
                                                   conv_b + (size_t)i*DI);
        gemm_x_k<<<dim3(1, ROWS/64), 256>>>(W_x + (size_t)i*DI*48);
        scan_seg1<<<B_*32*SEG, 256>>>(A_log + (size_t)i*DI*NS,
                                      W_dt + (size_t)i*DTR*DI,
                                      b_dt + (size_t)i*DI);
        scan_seg2<<<B_*32*SEG, 256>>>(A_log + (size_t)i*DI*NS,
                                      D_skip + (size_t)i*DI,
                                      W_dt + (size_t)i*DTR*DI,
                                      b_dt + (size_t)i*DI);
        gemm_out_k<<<dim3(DM/64, ROWS/64), 256>>>(W_out + (size_t)i*DI*DM);
    }

    head_kernel<<<ROWS, 256>>>(W_amp, b_amp, W_phase, b_phase, (float*)d_out);
}